// round 1
// baseline (speedup 1.0000x reference)
#include <cuda_runtime.h>
#include <math_constants.h>

// Problem constants (shapes fixed by the dataset)
#define NB    148      // persistent blocks (1/SM)
#define TM    64       // rows per tile
#define DF    128      // feature dim
#define OUTF  128      // hidden dim
#define BATCH 16       // anchors

#define XPAD  132      // padded row length (floats), mult of 4 for float4 STS/LDS
#define NPPAD 132
#define APAD  132
#define SPAD  68

// Shared layout (floats)
#define OFF_W   0
#define OFF_X   (OFF_W + OUTF*DF)          // 16384
#define OFF_NP  (OFF_X + TM*XPAD)          // +8448
#define OFF_ANC (OFF_NP + TM*NPPAD)        // +8448
#define OFF_W2  (OFF_ANC + BATCH*APAD)     // +2112
#define OFF_S   (OFF_W2 + 128)             // +128
#define OFF_SC  (OFF_S + BATCH*SPAD)       // +1088
#define OFF_MB  (OFF_SC + 16)
#define OFF_LB  (OFF_MB + 16)
#define SMEM_FLOATS (OFF_LB + 16)
#define SMEM_BYTES (SMEM_FLOATS * 4)       // 146,624 B

// Scratch (static device allocations are allowed)
__device__ float g_W1t[DF * OUTF];          // [k][o] = W1[o][128+k]
__device__ float g_anchor[BATCH * OUTF];    // [b][o]
__device__ float g_pm[NB * BATCH];
__device__ float g_pl[NB * BATCH];
__device__ float g_pv[NB * BATCH * DF];

// ---------------------------------------------------------------------------
// Prep: transpose node-half of W1 into global [k][o]; compute anchor part.
// ---------------------------------------------------------------------------
__global__ void prep_kernel(const float* __restrict__ xxa,
                            const float* __restrict__ W1) {
    int blk = blockIdx.x;
    if (blk < 64) {
        // W1t: 16384 elems, 64 blocks x 256 threads. Write-coalesced.
        int i = blk * 256 + threadIdx.x;     // i = k*128 + o
        int k = i >> 7, o = i & 127;
        g_W1t[i] = W1[o * 256 + 128 + k];
    } else {
        // anchor_part[b][o] = sum_d xxa[b][d] * W1[o][d]
        int b = blk - 64;
        __shared__ float xs[DF];
        if (threadIdx.x < DF) xs[threadIdx.x] = xxa[b * DF + threadIdx.x];
        __syncthreads();
        if (threadIdx.x < OUTF) {
            int o = threadIdx.x;
            const float* w = &W1[o * 256];
            float s = 0.f;
#pragma unroll 8
            for (int d = 0; d < DF; d++) s = fmaf(xs[d], w[d], s);
            g_anchor[b * OUTF + o] = s;
        }
    }
}

// ---------------------------------------------------------------------------
// Main fused kernel: NP-GEMM + scores + online softmax + pooling per 64-row tile
// ---------------------------------------------------------------------------
#define FMA4(i, xc, wv)                              \
    acc[i][0] = fmaf(xc, wv.x, acc[i][0]);           \
    acc[i][1] = fmaf(xc, wv.y, acc[i][1]);           \
    acc[i][2] = fmaf(xc, wv.z, acc[i][2]);           \
    acc[i][3] = fmaf(xc, wv.w, acc[i][3]);

__global__ __launch_bounds__(512, 1)
void main_kernel(const float* __restrict__ X,
                 const float* __restrict__ W2,
                 int M, int nTiles) {
    extern __shared__ float sm[];
    float* Wsh   = sm + OFF_W;
    float* Xsh   = sm + OFF_X;
    float* NPsh  = sm + OFF_NP;
    float* anc   = sm + OFF_ANC;
    float* w2sh  = sm + OFF_W2;
    float* s_sh  = sm + OFF_S;
    float* sc_sh = sm + OFF_SC;
    float* mb    = sm + OFF_MB;
    float* lb    = sm + OFF_LB;

    const int tid = threadIdx.x;
    const int tr = tid >> 5;     // warp id: row-group for GEMM, batch for softmax
    const int tc = tid & 31;

    // Block-persistent loads
#pragma unroll
    for (int it = 0; it < 32; it++) Wsh[tid + it * 512] = g_W1t[tid + it * 512];
    for (int i = tid; i < BATCH * OUTF; i += 512)
        anc[(i >> 7) * APAD + (i & 127)] = g_anchor[i];
    if (tid < 128) w2sh[tid] = W2[tid];
    if (tid < 16) { mb[tid] = -CUDART_INF_F; lb[tid] = 0.f; }

    float v0 = 0.f, v1 = 0.f, v2 = 0.f, v3 = 0.f;   // V[b=tr][tc + 32j]

    for (int t = blockIdx.x; t < nTiles; t += NB) {
        __syncthreads();   // protect Xsh/s_sh from previous iteration's readers

        // ---- Stage A: load X tile (row-major, padded), zero OOB rows ----
        const int m0 = t * TM;
#pragma unroll
        for (int it = 0; it < 4; it++) {
            int i4 = tid + it * 512;                 // 2048 float4s
            int r = i4 >> 5, c4 = (i4 & 31) * 4;
            int m = m0 + r;
            float4 val = make_float4(0.f, 0.f, 0.f, 0.f);
            if (m < M) val = *(const float4*)&X[(size_t)m * DF + c4];
            *(float4*)&Xsh[r * XPAD + c4] = val;
        }
        __syncthreads();

        // ---- Stage B: NP[r][o] = sum_k X[r][k] * Wt[k][o] (4x4 micro-tile) ----
        {
            float acc[4][4];
#pragma unroll
            for (int i = 0; i < 4; i++)
#pragma unroll
                for (int j = 0; j < 4; j++) acc[i][j] = 0.f;

            const float* x0p = &Xsh[(4 * tr + 0) * XPAD];
            const float* x1p = &Xsh[(4 * tr + 1) * XPAD];
            const float* x2p = &Xsh[(4 * tr + 2) * XPAD];
            const float* x3p = &Xsh[(4 * tr + 3) * XPAD];
            const float* wp  = &Wsh[4 * tc];

#pragma unroll 4
            for (int k = 0; k < DF; k += 4) {
                float4 xa = *(const float4*)(x0p + k);
                float4 xb = *(const float4*)(x1p + k);
                float4 xc = *(const float4*)(x2p + k);
                float4 xd = *(const float4*)(x3p + k);
                float4 w0 = *(const float4*)(wp + (k + 0) * OUTF);
                float4 w1 = *(const float4*)(wp + (k + 1) * OUTF);
                float4 w2 = *(const float4*)(wp + (k + 2) * OUTF);
                float4 w3 = *(const float4*)(wp + (k + 3) * OUTF);
                FMA4(0, xa.x, w0) FMA4(0, xa.y, w1) FMA4(0, xa.z, w2) FMA4(0, xa.w, w3)
                FMA4(1, xb.x, w0) FMA4(1, xb.y, w1) FMA4(1, xb.z, w2) FMA4(1, xb.w, w3)
                FMA4(2, xc.x, w0) FMA4(2, xc.y, w1) FMA4(2, xc.z, w2) FMA4(2, xc.w, w3)
                FMA4(3, xd.x, w0) FMA4(3, xd.y, w1) FMA4(3, xd.z, w2) FMA4(3, xd.w, w3)
            }
#pragma unroll
            for (int i = 0; i < 4; i++)
                *(float4*)&NPsh[(4 * tr + i) * NPPAD + 4 * tc] =
                    make_float4(acc[i][0], acc[i][1], acc[i][2], acc[i][3]);
        }
        __syncthreads();

        // ---- Stage C: scores s[b][r] = sum_o relu(anc[b][o]+NP[r][o])*W2[o] ----
#pragma unroll
        for (int half = 0; half < 2; half++) {
            int item = tid + half * 512;             // item = r*16 + b
            int r = item >> 4, b = item & 15;
            float s;
            if (m0 + r < M) {
                s = 0.f;
                const float* np = &NPsh[r * NPPAD];
                const float* ab = &anc[b * APAD];
#pragma unroll 4
                for (int o = 0; o < OUTF; o += 4) {
                    float4 n = *(const float4*)&np[o];
                    float4 a = *(const float4*)&ab[o];
                    float4 w = *(const float4*)&w2sh[o];
                    s = fmaf(fmaxf(n.x + a.x, 0.f), w.x, s);
                    s = fmaf(fmaxf(n.y + a.y, 0.f), w.y, s);
                    s = fmaf(fmaxf(n.z + a.z, 0.f), w.z, s);
                    s = fmaf(fmaxf(n.w + a.w, 0.f), w.w, s);
                }
            } else {
                s = -CUDART_INF_F;
            }
            s_sh[b * SPAD + r] = s;
        }
        __syncthreads();

        // ---- Stage D1: online softmax update, one warp per batch b ----
        {
            const int b = tr;
            float s0 = s_sh[b * SPAD + tc];
            float s1 = s_sh[b * SPAD + 32 + tc];
            float tmax = fmaxf(s0, s1);
#pragma unroll
            for (int off = 16; off; off >>= 1)
                tmax = fmaxf(tmax, __shfl_xor_sync(0xffffffffu, tmax, off));
            float mold = mb[b];
            float mnew = fmaxf(mold, tmax);
            float p0 = __expf(s0 - mnew);
            float p1 = __expf(s1 - mnew);
            s_sh[b * SPAD + tc] = p0;
            s_sh[b * SPAD + 32 + tc] = p1;
            float ps = p0 + p1;
#pragma unroll
            for (int off = 16; off; off >>= 1)
                ps += __shfl_xor_sync(0xffffffffu, ps, off);
            float scale = __expf(mold - mnew);       // 0 on first tile (exp(-inf))
            if (tc == 0) {
                mb[b] = mnew;
                lb[b] = lb[b] * scale + ps;
                sc_sh[b] = scale;
            }
        }
        __syncthreads();

        // ---- Stage D2: V[b][d] = V*scale + sum_r p[b][r] * X[r][d] ----
        {
            const float sc = sc_sh[tr];
            v0 *= sc; v1 *= sc; v2 *= sc; v3 *= sc;
            const float* ps = &s_sh[tr * SPAD];
#pragma unroll 2
            for (int r = 0; r < TM; r++) {
                float p = ps[r];
                const float* xr = &Xsh[r * XPAD + tc];
                v0 = fmaf(p, xr[0],  v0);
                v1 = fmaf(p, xr[32], v1);
                v2 = fmaf(p, xr[64], v2);
                v3 = fmaf(p, xr[96], v3);
            }
        }
    }
    __syncthreads();

    // ---- Emit per-block partials ----
    if (tid < 16) {
        g_pm[blockIdx.x * 16 + tid] = mb[tid];
        g_pl[blockIdx.x * 16 + tid] = lb[tid];
    }
    int base = blockIdx.x * BATCH * DF + tr * DF + tc;
    g_pv[base]      = v0;
    g_pv[base + 32] = v1;
    g_pv[base + 64] = v2;
    g_pv[base + 96] = v3;
}

// ---------------------------------------------------------------------------
// Finalize: combine 148 block partials per batch, normalize.
// ---------------------------------------------------------------------------
__global__ void final_kernel(float* __restrict__ out) {
    int b = blockIdx.x;
    int d = threadIdx.x;
    float Mx = -CUDART_INF_F;
    for (int j = 0; j < NB; j++) Mx = fmaxf(Mx, g_pm[j * 16 + b]);
    float L = 0.f, V = 0.f;
    for (int j = 0; j < NB; j++) {
        float f = __expf(g_pm[j * 16 + b] - Mx);
        L = fmaf(g_pl[j * 16 + b], f, L);
        V = fmaf(g_pv[j * BATCH * DF + b * DF + d], f, V);
    }
    out[b * DF + d] = V / L;
}

// ---------------------------------------------------------------------------
extern "C" void kernel_launch(void* const* d_in, const int* in_sizes, int n_in,
                              void* d_out, int out_size) {
    const float* xxa = (const float*)d_in[0];   // [16,128]
    const float* X   = (const float*)d_in[1];   // [M,128]
    // d_in[2] = adj (unused in forward math)
    const float* W1  = (const float*)d_in[3];   // [128,256]
    const float* W2  = (const float*)d_in[4];   // [1,128]
    float* out = (float*)d_out;                 // [16,128] fp32

    int M = in_sizes[1] / DF;
    int nTiles = (M + TM - 1) / TM;

    cudaFuncSetAttribute(main_kernel,
                         cudaFuncAttributeMaxDynamicSharedMemorySize, SMEM_BYTES);

    prep_kernel<<<80, 256>>>(xxa, W1);
    main_kernel<<<NB, 512, SMEM_BYTES>>>(X, W2, M, nTiles);
    final_kernel<<<16, 128>>>(out);
}

// round 2
// speedup vs baseline: 1.0671x; 1.0671x over previous
#include <cuda_runtime.h>
#include <math_constants.h>

// Problem constants (shapes fixed by the dataset)
#define NB    148      // persistent blocks (1/SM)
#define TM    64       // rows per tile
#define DF    128      // feature dim
#define OUTF  128      // hidden dim
#define BATCH 16       // anchors

#define XPAD  132      // padded row length (floats)
#define NPPAD 132
#define APAD  132
#define SROW  18       // transposed score row stride [r][b], 18 => 2-way conflicts max

// Shared layout (floats)
#define OFF_W   0
#define OFF_X   (OFF_W + OUTF*DF)          // 16384
#define OFF_NP  (OFF_X + TM*XPAD)
#define OFF_ANC (OFF_NP + TM*NPPAD)
#define OFF_W2  (OFF_ANC + BATCH*APAD)
#define OFF_S   (OFF_W2 + 128)
#define OFF_SC  (OFF_S + TM*SROW)
#define OFF_MB  (OFF_SC + 16)
#define OFF_LB  (OFF_MB + 16)
#define SMEM_FLOATS (OFF_LB + 16)
#define SMEM_BYTES (SMEM_FLOATS * 4)

typedef unsigned long long ull;

// ---------------- packed f32x2 helpers (sm_103a) ----------------
__device__ __forceinline__ ull ffma2(ull a, ull b, ull c) {
    ull d; asm("fma.rn.f32x2 %0, %1, %2, %3;" : "=l"(d) : "l"(a), "l"(b), "l"(c)); return d;
}
__device__ __forceinline__ ull fadd2(ull a, ull b) {
    ull d; asm("add.rn.f32x2 %0, %1, %2;" : "=l"(d) : "l"(a), "l"(b)); return d;
}
__device__ __forceinline__ ull fmul2(ull a, ull b) {
    ull d; asm("mul.rn.f32x2 %0, %1, %2;" : "=l"(d) : "l"(a), "l"(b)); return d;
}
__device__ __forceinline__ ull dup2(float x) {
    ull d; unsigned u = __float_as_uint(x);
    asm("mov.b64 %0, {%1, %2};" : "=l"(d) : "r"(u), "r"(u)); return d;
}
__device__ __forceinline__ float2 unpk(ull v) {
    float2 r; asm("mov.b64 {%0, %1}, %2;" : "=f"(r.x), "=f"(r.y) : "l"(v)); return r;
}

// Scratch (static device allocations are allowed)
__device__ float g_W1t[DF * OUTF];          // [k][o] = W1[o][128+k]
__device__ float g_anchor[BATCH * OUTF];    // [b][o]
__device__ float g_pm[NB * BATCH];
__device__ float g_pl[NB * BATCH];
__device__ float g_pv[NB * BATCH * DF];

// ---------------------------------------------------------------------------
// Prep: transpose node-half of W1 into global [k][o]; compute anchor part.
// ---------------------------------------------------------------------------
__global__ void prep_kernel(const float* __restrict__ xxa,
                            const float* __restrict__ W1) {
    int blk = blockIdx.x;
    if (blk < 64) {
        int i = blk * 256 + threadIdx.x;     // i = k*128 + o
        int k = i >> 7, o = i & 127;
        g_W1t[i] = W1[o * 256 + 128 + k];
    } else {
        int b = blk - 64;
        __shared__ float xs[DF];
        if (threadIdx.x < DF) xs[threadIdx.x] = xxa[b * DF + threadIdx.x];
        __syncthreads();
        if (threadIdx.x < OUTF) {
            int o = threadIdx.x;
            const float* w = &W1[o * 256];
            float s = 0.f;
#pragma unroll 8
            for (int d = 0; d < DF; d++) s = fmaf(xs[d], w[d], s);
            g_anchor[b * OUTF + o] = s;
        }
    }
}

// ---------------------------------------------------------------------------
// Main fused kernel
// ---------------------------------------------------------------------------
#define ROWSUB(i, xs, wv)                              \
    { ull xdp = dup2(xs);                              \
      a2[i][0] = ffma2(xdp, wv.x, a2[i][0]);           \
      a2[i][1] = ffma2(xdp, wv.y, a2[i][1]); }

__global__ __launch_bounds__(512, 1)
void main_kernel(const float* __restrict__ X,
                 const float* __restrict__ W2,
                 int M, int nTiles) {
    extern __shared__ float sm[];
    float* Wsh   = sm + OFF_W;
    float* Xsh   = sm + OFF_X;
    float* NPsh  = sm + OFF_NP;
    float* anc   = sm + OFF_ANC;
    float* w2sh  = sm + OFF_W2;
    float* s_sh  = sm + OFF_S;        // transposed: [r][b], stride SROW
    float* sc_sh = sm + OFF_SC;
    float* mb    = sm + OFF_MB;
    float* lb    = sm + OFF_LB;

    const int tid = threadIdx.x;
    const int tr = tid >> 5;     // warp id
    const int tc = tid & 31;

    // D2/pooling ownership: thread owns V[b0..b0+3][dd]
    const int dd = tid & 127;
    const int b0 = (tid >> 7) * 4;

    // Block-persistent loads
#pragma unroll
    for (int it = 0; it < 32; it++) Wsh[tid + it * 512] = g_W1t[tid + it * 512];
    for (int i = tid; i < BATCH * OUTF; i += 512)
        anc[(i >> 7) * APAD + (i & 127)] = g_anchor[i];
    if (tid < 128) w2sh[tid] = W2[tid];
    if (tid < 16) { mb[tid] = -CUDART_INF_F; lb[tid] = 0.f; }

    ull v01 = 0ull, v23 = 0ull;    // packed V accumulators (b0,b0+1),(b0+2,b0+3)

    for (int t = blockIdx.x; t < nTiles; t += NB) {
        __syncthreads();   // protect Xsh/s_sh from previous iteration's readers

        // ---- Stage A: load X tile (row-major, padded), zero OOB rows ----
        const int m0 = t * TM;
#pragma unroll
        for (int it = 0; it < 4; it++) {
            int i4 = tid + it * 512;                 // 2048 float4s
            int r = i4 >> 5, c4 = (i4 & 31) * 4;
            int m = m0 + r;
            float4 val = make_float4(0.f, 0.f, 0.f, 0.f);
            if (m < M) val = *(const float4*)&X[(size_t)m * DF + c4];
            *(float4*)&Xsh[r * XPAD + c4] = val;
        }
        __syncthreads();

        // ---- Stage B: NP[r][o] = sum_k X[r][k] * Wt[k][o], packed f32x2 ----
        {
            ull a2[4][2];
#pragma unroll
            for (int i = 0; i < 4; i++) { a2[i][0] = 0ull; a2[i][1] = 0ull; }

            const float* x0p = &Xsh[(4 * tr + 0) * XPAD];
            const float* x1p = &Xsh[(4 * tr + 1) * XPAD];
            const float* x2p = &Xsh[(4 * tr + 2) * XPAD];
            const float* x3p = &Xsh[(4 * tr + 3) * XPAD];
            const float* wp  = &Wsh[4 * tc];

#pragma unroll 4
            for (int k = 0; k < DF; k += 4) {
                float4 xa = *(const float4*)(x0p + k);
                float4 xb = *(const float4*)(x1p + k);
                float4 xc = *(const float4*)(x2p + k);
                float4 xd = *(const float4*)(x3p + k);
                ulonglong2 w0 = *(const ulonglong2*)(wp + (k + 0) * OUTF);
                ulonglong2 w1 = *(const ulonglong2*)(wp + (k + 1) * OUTF);
                ulonglong2 w2 = *(const ulonglong2*)(wp + (k + 2) * OUTF);
                ulonglong2 w3 = *(const ulonglong2*)(wp + (k + 3) * OUTF);
                ROWSUB(0, xa.x, w0) ROWSUB(1, xb.x, w0) ROWSUB(2, xc.x, w0) ROWSUB(3, xd.x, w0)
                ROWSUB(0, xa.y, w1) ROWSUB(1, xb.y, w1) ROWSUB(2, xc.y, w1) ROWSUB(3, xd.y, w1)
                ROWSUB(0, xa.z, w2) ROWSUB(1, xb.z, w2) ROWSUB(2, xc.z, w2) ROWSUB(3, xd.z, w2)
                ROWSUB(0, xa.w, w3) ROWSUB(1, xb.w, w3) ROWSUB(2, xc.w, w3) ROWSUB(3, xd.w, w3)
            }
#pragma unroll
            for (int i = 0; i < 4; i++)
                *(ulonglong2*)&NPsh[(4 * tr + i) * NPPAD + 4 * tc] =
                    make_ulonglong2(a2[i][0], a2[i][1]);
        }
        __syncthreads();

        // ---- Stage C: scores s[b][r] = sum_o relu(anc+NP)*W2, packed adds ----
#pragma unroll
        for (int half = 0; half < 2; half++) {
            int item = tid + half * 512;             // item = r*16 + b
            int r = item >> 4, b = item & 15;
            float s;
            if (m0 + r < M) {
                float sA = 0.f, sB = 0.f;
                const float* np = &NPsh[r * NPPAD];
                const float* ab = &anc[b * APAD];
#pragma unroll 8
                for (int o = 0; o < OUTF; o += 4) {
                    ulonglong2 n2 = *(const ulonglong2*)&np[o];
                    ulonglong2 av = *(const ulonglong2*)&ab[o];
                    float4 w = *(const float4*)&w2sh[o];
                    float2 f01 = unpk(fadd2(n2.x, av.x));
                    float2 f23 = unpk(fadd2(n2.y, av.y));
                    sA = fmaf(fmaxf(f01.x, 0.f), w.x, sA);
                    sB = fmaf(fmaxf(f01.y, 0.f), w.y, sB);
                    sA = fmaf(fmaxf(f23.x, 0.f), w.z, sA);
                    sB = fmaf(fmaxf(f23.y, 0.f), w.w, sB);
                }
                s = sA + sB;
            } else {
                s = -CUDART_INF_F;
            }
            s_sh[r * SROW + b] = s;
        }
        __syncthreads();

        // ---- Stage D1: online softmax update, one warp per batch b ----
        {
            const int b = tr;
            float s0 = s_sh[tc * SROW + b];
            float s1 = s_sh[(32 + tc) * SROW + b];
            float tmax = fmaxf(s0, s1);
#pragma unroll
            for (int off = 16; off; off >>= 1)
                tmax = fmaxf(tmax, __shfl_xor_sync(0xffffffffu, tmax, off));
            float mold = mb[b];
            float mnew = fmaxf(mold, tmax);
            float p0 = __expf(s0 - mnew);
            float p1 = __expf(s1 - mnew);
            s_sh[tc * SROW + b] = p0;
            s_sh[(32 + tc) * SROW + b] = p1;
            float ps = p0 + p1;
#pragma unroll
            for (int off = 16; off; off >>= 1)
                ps += __shfl_xor_sync(0xffffffffu, ps, off);
            float scale = __expf(mold - mnew);       // 0 on first tile
            if (tc == 0) {
                mb[b] = mnew;
                lb[b] = lb[b] * scale + ps;
                sc_sh[b] = scale;
            }
        }
        __syncthreads();

        // ---- Stage D2: V[b][d] += sum_r p[b][r]*X[r][d], packed over b-pairs ----
        {
            ull sc01 = *(const ull*)&sc_sh[b0];
            ull sc23 = *(const ull*)&sc_sh[b0 + 2];
            v01 = fmul2(v01, sc01);
            v23 = fmul2(v23, sc23);
#pragma unroll 4
            for (int r = 0; r < TM; r++) {
                float x = Xsh[r * XPAD + dd];
                ull xd = dup2(x);
                ull p01 = *(const ull*)&s_sh[r * SROW + b0];
                ull p23 = *(const ull*)&s_sh[r * SROW + b0 + 2];
                v01 = ffma2(xd, p01, v01);
                v23 = ffma2(xd, p23, v23);
            }
        }
    }
    __syncthreads();

    // ---- Emit per-block partials ----
    if (tid < 16) {
        g_pm[blockIdx.x * 16 + tid] = mb[tid];
        g_pl[blockIdx.x * 16 + tid] = lb[tid];
    }
    {
        float2 e01 = unpk(v01), e23 = unpk(v23);
        int base = blockIdx.x * BATCH * DF + b0 * DF + dd;
        g_pv[base]           = e01.x;
        g_pv[base + DF]      = e01.y;
        g_pv[base + 2 * DF]  = e23.x;
        g_pv[base + 3 * DF]  = e23.y;
    }
}

// ---------------------------------------------------------------------------
// Finalize: combine 148 block partials per batch, normalize.
// ---------------------------------------------------------------------------
__global__ void final_kernel(float* __restrict__ out) {
    int b = blockIdx.x;
    int d = threadIdx.x;
    float Mx = -CUDART_INF_F;
    for (int j = 0; j < NB; j++) Mx = fmaxf(Mx, g_pm[j * 16 + b]);
    float L = 0.f, V = 0.f;
    for (int j = 0; j < NB; j++) {
        float f = __expf(g_pm[j * 16 + b] - Mx);
        L = fmaf(g_pl[j * 16 + b], f, L);
        V = fmaf(g_pv[j * BATCH * DF + b * DF + d], f, V);
    }
    out[b * DF + d] = V / L;
}

// ---------------------------------------------------------------------------
extern "C" void kernel_launch(void* const* d_in, const int* in_sizes, int n_in,
                              void* d_out, int out_size) {
    const float* xxa = (const float*)d_in[0];   // [16,128]
    const float* X   = (const float*)d_in[1];   // [M,128]
    // d_in[2] = adj (unused in forward math)
    const float* W1  = (const float*)d_in[3];   // [128,256]
    const float* W2  = (const float*)d_in[4];   // [1,128]
    float* out = (float*)d_out;                 // [16,128] fp32

    int M = in_sizes[1] / DF;
    int nTiles = (M + TM - 1) / TM;

    cudaFuncSetAttribute(main_kernel,
                         cudaFuncAttributeMaxDynamicSharedMemorySize, SMEM_BYTES);

    prep_kernel<<<80, 256>>>(xxa, W1);
    main_kernel<<<NB, 512, SMEM_BYTES>>>(X, W2, M, nTiles);
    final_kernel<<<16, 128>>>(out);
}